// round 6
// baseline (speedup 1.0000x reference)
#include <cuda_runtime.h>
#include <math.h>
#include <stdint.h>
#include <stdio.h>

#define BB    32
#define LL    1024
#define BLROWS (BB*LL)          // 32768
#define HID   512
#define G4    2048
#define NUMC  1000
#define ATTD  80
#define LCTAS 128

// ---------------- scratch (static device globals: allocation-free) ----------
__device__ float g_sae  [(size_t)BLROWS * HID];    // LSTM input rows
__device__ float g_xpre [(size_t)BLROWS * G4];     // x @ W_ih^T + b
__device__ float g_hout [(size_t)BLROWS * HID];    // LSTM hidden states ("out")
__device__ float g_attT [(size_t)BLROWS * ATTD];   // tanh(out @ mlp_W^T + b)
__device__ float g_att  [BLROWS];                  // per-position attention logit
__device__ float g_final[(size_t)BLROWS * (2*HID)];// [attn_cum_1, out]
__device__ unsigned g_bar_count;
__device__ unsigned g_bar_phase;

// ---------------- embedding gather ------------------------------------------
__global__ void embed_kernel(const int* __restrict__ skill,
                             const int* __restrict__ answer,
                             const float* __restrict__ skill_table,
                             const float* __restrict__ answer_table)
{
    int idx = blockIdx.x * blockDim.x + threadIdx.x;   // over BLROWS*128 float4
    int row = idx >> 7;
    int q   = idx & 127;
    if (row >= BLROWS) return;
    int sk = skill[row];
    int an = answer[row];
    const float4* se = (const float4*)(skill_table  + (size_t)sk * 256);
    const float4* ae = (const float4*)(answer_table + (size_t)an * 256);
    float4 v;
    if (an == 1) v = (q < 64) ? se[q] : ae[q - 64];   // [skill, answer]
    else         v = (q < 64) ? ae[q] : se[q - 64];   // [answer, skill]
    ((float4*)g_sae)[(size_t)row * 128 + q] = v;
}

// ---------------- fp32 SGEMM: C = op(A @ B^T + bias1 + bias2) ---------------
// A: (M,K) row-major, B: (N,K) row-major, C: (M,N) row-major.
// M must be a multiple of 128. N,K arbitrary multiples of (1, 8). 256 threads.
// OP: 0 = identity, 1 = tanh, 2 = sigmoid
template<int OP>
__global__ void __launch_bounds__(256)
sgemm_nt(const float* __restrict__ A, const float* __restrict__ Bm,
         const float* __restrict__ bias1, const float* __restrict__ bias2,
         float* __restrict__ C, int M, int N, int K)
{
    __shared__ float As[8][128];
    __shared__ float Bs[8][128];

    const int tid = threadIdx.x;
    const int bm = blockIdx.y * 128;
    const int bn = blockIdx.x * 128;
    const int lr = tid >> 1;          // 0..127 tile row
    const int lc = (tid & 1) * 4;     // 0 or 4 (k offset)
    const int tx = tid & 15;
    const int ty = tid >> 4;

    float acc[8][8];
    #pragma unroll
    for (int i = 0; i < 8; i++)
        #pragma unroll
        for (int j = 0; j < 8; j++) acc[i][j] = 0.f;

    for (int k0 = 0; k0 < K; k0 += 8) {
        float4 a4 = *(const float4*)(A + (size_t)(bm + lr) * K + k0 + lc);
        As[lc+0][lr] = a4.x; As[lc+1][lr] = a4.y;
        As[lc+2][lr] = a4.z; As[lc+3][lr] = a4.w;

        float4 b4 = make_float4(0.f, 0.f, 0.f, 0.f);
        if (bn + lr < N)
            b4 = *(const float4*)(Bm + (size_t)(bn + lr) * K + k0 + lc);
        Bs[lc+0][lr] = b4.x; Bs[lc+1][lr] = b4.y;
        Bs[lc+2][lr] = b4.z; Bs[lc+3][lr] = b4.w;
        __syncthreads();

        #pragma unroll
        for (int kk = 0; kk < 8; kk++) {
            float a[8], b[8];
            *(float4*)(a)     = *(const float4*)&As[kk][ty*4];
            *(float4*)(a + 4) = *(const float4*)&As[kk][64 + ty*4];
            *(float4*)(b)     = *(const float4*)&Bs[kk][tx*4];
            *(float4*)(b + 4) = *(const float4*)&Bs[kk][64 + tx*4];
            #pragma unroll
            for (int i = 0; i < 8; i++)
                #pragma unroll
                for (int j = 0; j < 8; j++)
                    acc[i][j] += a[i] * b[j];
        }
        __syncthreads();
    }

    #pragma unroll
    for (int i = 0; i < 8; i++) {
        int row = bm + ((i < 4) ? (ty*4 + i) : (64 + ty*4 + i - 4));
        #pragma unroll
        for (int j = 0; j < 8; j++) {
            int col = bn + ((j < 4) ? (tx*4 + j) : (64 + tx*4 + j - 4));
            if (col < N) {
                float v = acc[i][j];
                if (bias1) v += bias1[col];
                if (bias2) v += bias2[col];
                if (OP == 1)      v = tanhf(v);
                else if (OP == 2) v = 1.f / (1.f + expf(-v));
                C[(size_t)row * N + col] = v;
            }
        }
    }
}

// ---------------- persistent LSTM (128 CTAs, grid barrier) ------------------
__device__ __forceinline__ void grid_barrier(int ncta)
{
    __threadfence();
    __syncthreads();
    if (threadIdx.x == 0) {
        volatile unsigned* ph_p = &g_bar_phase;
        unsigned ph = *ph_p;
        unsigned prev = atomicAdd(&g_bar_count, 1u);
        if (prev == (unsigned)(ncta - 1)) {
            g_bar_count = 0;
            __threadfence();
            *ph_p = ph + 1;
        } else {
            while (*ph_p == ph) { __nanosleep(32); }
        }
    }
    __syncthreads();
}

// Each CTA owns 4 hidden units (16 gate rows of W_hh) cached in SMEM forever.
// Per step: all CTAs read h[t-1] (global, L2), compute their 16 gate rows for
// all 32 batches, apply gates, write their 4 h values per batch, barrier.
__global__ void __launch_bounds__(256)
lstm_kernel(const float* __restrict__ xpre, const float* __restrict__ W_hh,
            float* __restrict__ hout)
{
    extern __shared__ float sm[];
    float* W_s = sm;                 // 16 rows x 516 (padded)
    float* h_s = sm + 16 * 516;      // 32 x 512
    __shared__ float gate_s[32][16];
    __shared__ float c_s[32][4];

    const int tid = threadIdx.x;
    const int cta = blockIdx.x;
    const int bg = tid >> 4;         // 0..15 -> batches (2*bg, 2*bg+1)
    const int r  = tid & 15;         // 0..15 -> gate row within slice
    const int b0 = bg * 2, b1 = bg * 2 + 1;
    const int grow = (r >> 2) * 512 + cta * 4 + (r & 3); // global gate row

    // load W_hh slice once
    for (int i = tid; i < 16 * 512; i += 256) {
        int rr = i >> 9, kk = i & 511;
        int gr = (rr >> 2) * 512 + cta * 4 + (rr & 3);
        W_s[rr * 516 + kk] = W_hh[(size_t)gr * 512 + kk];
    }
    if (tid < 128) c_s[tid >> 2][tid & 3] = 0.f;
    __syncthreads();

    const float4* Wr4 = (const float4*)(W_s + r * 516);
    const float4* H04 = (const float4*)(h_s + b0 * 512);
    const float4* H14 = (const float4*)(h_s + b1 * 512);

    for (int t = 0; t < LL; t++) {
        if (t > 0) {
            // broadcast h[t-1] for all 32 batches into SMEM (L2-only loads)
            for (int i = tid; i < 32 * 128; i += 256) {
                int b = i >> 7, kq = i & 127;
                ((float4*)h_s)[b * 128 + kq] =
                    __ldcg(((const float4*)hout) + ((size_t)b * LL + (t - 1)) * 128 + kq);
            }
        }
        __syncthreads();

        float4 A0 = make_float4(0,0,0,0), A1 = make_float4(0,0,0,0);
        if (t > 0) {
            #pragma unroll 8
            for (int kq = 0; kq < 128; kq++) {
                float4 w  = Wr4[kq];
                float4 x0 = H04[kq];
                float4 x1 = H14[kq];
                A0.x += w.x * x0.x; A0.y += w.y * x0.y;
                A0.z += w.z * x0.z; A0.w += w.w * x0.w;
                A1.x += w.x * x1.x; A1.y += w.y * x1.y;
                A1.z += w.z * x1.z; A1.w += w.w * x1.w;
            }
        }
        float acc0 = (A0.x + A0.y) + (A0.z + A0.w);
        float acc1 = (A1.x + A1.y) + (A1.z + A1.w);
        acc0 += __ldg(xpre + ((size_t)b0 * LL + t) * G4 + grow);
        acc1 += __ldg(xpre + ((size_t)b1 * LL + t) * G4 + grow);
        gate_s[b0][r] = acc0;
        gate_s[b1][r] = acc1;
        __syncthreads();

        if (tid < 128) {
            int b = tid >> 2, u = tid & 3;
            float gi = gate_s[b][u];
            float gf = gate_s[b][4 + u];
            float gc = gate_s[b][8 + u];
            float go = gate_s[b][12 + u];
            float i_ = 1.f / (1.f + expf(-gi));
            float f_ = 1.f / (1.f + expf(-gf));
            float gg = tanhf(gc);
            float o_ = 1.f / (1.f + expf(-go));
            float c  = f_ * c_s[b][u] + i_ * gg;
            c_s[b][u] = c;
            hout[((size_t)b * LL + t) * HID + cta * 4 + u] = o_ * tanhf(c);
        }
        grid_barrier(LCTAS);
    }
}

// ---------------- att[m] = attT[m,:] . sim_W --------------------------------
__global__ void att_reduce(const float* __restrict__ attT,
                           const float* __restrict__ simW,
                           float* __restrict__ att)
{
    int gid  = blockIdx.x * blockDim.x + threadIdx.x;
    int row  = gid >> 5;
    int lane = threadIdx.x & 31;
    if (row >= BLROWS) return;
    float v = 0.f;
    for (int a = lane; a < ATTD; a += 32)
        v += attT[(size_t)row * ATTD + a] * simW[a];
    #pragma unroll
    for (int o = 16; o; o >>= 1) v += __shfl_down_sync(0xffffffffu, v, o);
    if (lane == 0) att[row] = v;
}

// ---------------- causal attention via online-softmax prefix scan -----------
// alphas[b,i,j] = exp(att[b,j]) / sum_{k<=i} exp(att[b,k])  (j<=i)
// attn_out[b,i] = prefix_num / prefix_den; attn_cum_1 = exclusive cumsum.
// Writes final[b,i] = [attn_cum_1 (512), out (512)].
__global__ void attn_scan(const float* __restrict__ att,
                          const float* __restrict__ out,
                          float* __restrict__ finalbuf)
{
    int b = blockIdx.x;          // 32 blocks
    int h = threadIdx.x;         // 512 threads
    __shared__ float s_att[LL];
    for (int i = h; i < LL; i += 512) s_att[i] = att[(size_t)b * LL + i];
    __syncthreads();

    const float* ob = out      + (size_t)b * LL * HID;
    float*       fb = finalbuf + (size_t)b * LL * (2 * HID);

    float m = -1e30f, den = 0.f, num = 0.f, cum = 0.f;
    for (int i = 0; i < LL; i++) {
        float s     = s_att[i];
        float mnew  = fmaxf(m, s);
        float scale = expf(m - mnew);
        float alpha = expf(s - mnew);
        float ov    = ob[(size_t)i * HID + h];
        num = num * scale + alpha * ov;
        den = den * scale + alpha;
        m   = mnew;
        fb[(size_t)i * (2 * HID) + h]       = cum;   // attn_cum_1 (exclusive)
        fb[(size_t)i * (2 * HID) + HID + h] = ov;    // out
        cum += num / den;
    }
}

// ---------------- launch -----------------------------------------------------
extern "C" void kernel_launch(void* const* d_in, const int* in_sizes, int n_in,
                              void* d_out, int out_size)
{
    const int*   skill        = (const int*)  d_in[0];
    const int*   answer       = (const int*)  d_in[1];
    const float* skill_table  = (const float*)d_in[2];
    const float* answer_table = (const float*)d_in[3];
    const float* W_ih         = (const float*)d_in[4];
    const float* W_hh         = (const float*)d_in[5];
    const float* b_ih         = (const float*)d_in[6];
    const float* b_hh         = (const float*)d_in[7];
    const float* mlp_W        = (const float*)d_in[8];
    const float* mlp_b        = (const float*)d_in[9];
    const float* sim_W        = (const float*)d_in[10];
    const float* fc_W         = (const float*)d_in[11];
    const float* fc_b         = (const float*)d_in[12];
    float* outp = (float*)d_out;

    float *p_sae, *p_xpre, *p_hout, *p_attT, *p_att, *p_final;
    cudaGetSymbolAddress((void**)&p_sae,   g_sae);
    cudaGetSymbolAddress((void**)&p_xpre,  g_xpre);
    cudaGetSymbolAddress((void**)&p_hout,  g_hout);
    cudaGetSymbolAddress((void**)&p_attT,  g_attT);
    cudaGetSymbolAddress((void**)&p_att,   g_att);
    cudaGetSymbolAddress((void**)&p_final, g_final);

    // 1) embeddings -> sae
    {
        int total = BLROWS * 128;
        embed_kernel<<<total / 256, 256>>>(skill, answer, skill_table, answer_table);
    }

    // 2) x_pre = sae @ W_ih^T + (b_ih + b_hh)
    {
        dim3 grid(G4 / 128, BLROWS / 128);
        sgemm_nt<0><<<grid, 256>>>(p_sae, W_ih, b_ih, b_hh, p_xpre,
                                   BLROWS, G4, HID);
    }

    // 3) LSTM recurrence (persistent, grid barrier)
    {
        const int smem = (16 * 516 + 32 * 512) * (int)sizeof(float);  // 98560
        cudaFuncSetAttribute(lstm_kernel,
                             cudaFuncAttributeMaxDynamicSharedMemorySize, smem);
        lstm_kernel<<<LCTAS, 256, smem>>>(p_xpre, W_hh, p_hout);
    }

    // 4) attT = tanh(out @ mlp_W^T + mlp_b)
    {
        dim3 grid((ATTD + 127) / 128, BLROWS / 128);
        sgemm_nt<1><<<grid, 256>>>(p_hout, mlp_W, mlp_b, nullptr, p_attT,
                                   BLROWS, ATTD, HID);
    }

    // 5) att = attT . sim_W
    att_reduce<<<(BLROWS * 32) / 256, 256>>>(p_attT, sim_W, p_att);

    // 6) online-softmax prefix scan -> final = [attn_cum_1, out]
    attn_scan<<<BB, 512>>>(p_att, p_hout, p_final);

    // 7) res = sigmoid(final @ fc_W^T + fc_b)
    {
        dim3 grid((NUMC + 127) / 128, BLROWS / 128);
        sgemm_nt<2><<<grid, 256>>>(p_final, fc_W, fc_b, nullptr, outp,
                                   BLROWS, NUMC, 2 * HID);
    }
}

// round 7
// speedup vs baseline: 1.0041x; 1.0041x over previous
#include <cuda_runtime.h>
#include <math.h>
#include <stdint.h>
#include <stdio.h>

#define BB    32
#define LL    1024
#define BLROWS (BB*LL)          // 32768
#define HID   512
#define G4    2048
#define NUMC  1000
#define ATTD  80
#define LCTAS 128

// ---------------- scratch (static device globals: allocation-free) ----------
__device__ float g_sae  [(size_t)BLROWS * HID];    // LSTM input rows
__device__ float g_xpre [(size_t)BLROWS * G4];     // x @ W_ih^T + b
__device__ float g_hout [(size_t)BLROWS * HID];    // LSTM hidden states ("out")
__device__ float g_attT [(size_t)BLROWS * ATTD];   // tanh(out @ mlp_W^T + b)
__device__ float g_att  [BLROWS];                  // per-position attention logit
__device__ float g_final[(size_t)BLROWS * (2*HID)];// [attn_cum_1, out]
__device__ unsigned g_bar_count;
__device__ unsigned g_bar_phase;

// ---------------- embedding gather ------------------------------------------
__global__ void embed_kernel(const int* __restrict__ skill,
                             const int* __restrict__ answer,
                             const float* __restrict__ skill_table,
                             const float* __restrict__ answer_table)
{
    int idx = blockIdx.x * blockDim.x + threadIdx.x;   // over BLROWS*128 float4
    int row = idx >> 7;
    int q   = idx & 127;
    if (row >= BLROWS) return;
    int sk = skill[row];
    int an = answer[row];
    const float4* se = (const float4*)(skill_table  + (size_t)sk * 256);
    const float4* ae = (const float4*)(answer_table + (size_t)an * 256);
    float4 v;
    if (an == 1) v = (q < 64) ? se[q] : ae[q - 64];   // [skill, answer]
    else         v = (q < 64) ? ae[q] : se[q - 64];   // [answer, skill]
    ((float4*)g_sae)[(size_t)row * 128 + q] = v;
}

// ---------------- fp32 SGEMM: C = op(A @ B^T + bias1 + bias2) ---------------
// A: (M,K) row-major, B: (N,K) row-major, C: (M,N) row-major.
// M must be a multiple of 128. N,K arbitrary multiples of (1, 8). 256 threads.
// OP: 0 = identity, 1 = tanh, 2 = sigmoid
template<int OP>
__global__ void __launch_bounds__(256)
sgemm_nt(const float* __restrict__ A, const float* __restrict__ Bm,
         const float* __restrict__ bias1, const float* __restrict__ bias2,
         float* __restrict__ C, int M, int N, int K)
{
    __shared__ float As[8][128];
    __shared__ float Bs[8][128];

    const int tid = threadIdx.x;
    const int bm = blockIdx.y * 128;
    const int bn = blockIdx.x * 128;
    const int lr = tid >> 1;          // 0..127 tile row
    const int lc = (tid & 1) * 4;     // 0 or 4 (k offset)
    const int tx = tid & 15;
    const int ty = tid >> 4;

    float acc[8][8];
    #pragma unroll
    for (int i = 0; i < 8; i++)
        #pragma unroll
        for (int j = 0; j < 8; j++) acc[i][j] = 0.f;

    for (int k0 = 0; k0 < K; k0 += 8) {
        float4 a4 = *(const float4*)(A + (size_t)(bm + lr) * K + k0 + lc);
        As[lc+0][lr] = a4.x; As[lc+1][lr] = a4.y;
        As[lc+2][lr] = a4.z; As[lc+3][lr] = a4.w;

        float4 b4 = make_float4(0.f, 0.f, 0.f, 0.f);
        if (bn + lr < N)
            b4 = *(const float4*)(Bm + (size_t)(bn + lr) * K + k0 + lc);
        Bs[lc+0][lr] = b4.x; Bs[lc+1][lr] = b4.y;
        Bs[lc+2][lr] = b4.z; Bs[lc+3][lr] = b4.w;
        __syncthreads();

        #pragma unroll
        for (int kk = 0; kk < 8; kk++) {
            float a[8], b[8];
            *(float4*)(a)     = *(const float4*)&As[kk][ty*4];
            *(float4*)(a + 4) = *(const float4*)&As[kk][64 + ty*4];
            *(float4*)(b)     = *(const float4*)&Bs[kk][tx*4];
            *(float4*)(b + 4) = *(const float4*)&Bs[kk][64 + tx*4];
            #pragma unroll
            for (int i = 0; i < 8; i++)
                #pragma unroll
                for (int j = 0; j < 8; j++)
                    acc[i][j] += a[i] * b[j];
        }
        __syncthreads();
    }

    #pragma unroll
    for (int i = 0; i < 8; i++) {
        int row = bm + ((i < 4) ? (ty*4 + i) : (64 + ty*4 + i - 4));
        #pragma unroll
        for (int j = 0; j < 8; j++) {
            int col = bn + ((j < 4) ? (tx*4 + j) : (64 + tx*4 + j - 4));
            if (col < N) {
                float v = acc[i][j];
                if (bias1) v += bias1[col];
                if (bias2) v += bias2[col];
                if (OP == 1)      v = tanhf(v);
                else if (OP == 2) v = 1.f / (1.f + expf(-v));
                C[(size_t)row * N + col] = v;
            }
        }
    }
}

// ---------------- persistent LSTM (128 CTAs, grid barrier) ------------------
__device__ __forceinline__ void grid_barrier(int ncta)
{
    __threadfence();
    __syncthreads();
    if (threadIdx.x == 0) {
        volatile unsigned* ph_p = &g_bar_phase;
        unsigned ph = *ph_p;
        unsigned prev = atomicAdd(&g_bar_count, 1u);
        if (prev == (unsigned)(ncta - 1)) {
            g_bar_count = 0;
            __threadfence();
            *ph_p = ph + 1;
        } else {
            while (*ph_p == ph) { __nanosleep(32); }
        }
    }
    __syncthreads();
}

// Each CTA owns 4 hidden units (16 gate rows of W_hh) cached in SMEM forever.
// Per step: all CTAs read h[t-1] (global, L2), compute their 16 gate rows for
// all 32 batches, apply gates, write their 4 h values per batch, barrier.
__global__ void __launch_bounds__(256)
lstm_kernel(const float* __restrict__ xpre, const float* __restrict__ W_hh,
            float* __restrict__ hout)
{
    extern __shared__ float sm[];
    float* W_s = sm;                 // 16 rows x 516 (padded)
    float* h_s = sm + 16 * 516;      // 32 x 512
    __shared__ float gate_s[32][16];
    __shared__ float c_s[32][4];

    const int tid = threadIdx.x;
    const int cta = blockIdx.x;
    const int bg = tid >> 4;         // 0..15 -> batches (2*bg, 2*bg+1)
    const int r  = tid & 15;         // 0..15 -> gate row within slice
    const int b0 = bg * 2, b1 = bg * 2 + 1;
    const int grow = (r >> 2) * 512 + cta * 4 + (r & 3); // global gate row

    // load W_hh slice once
    for (int i = tid; i < 16 * 512; i += 256) {
        int rr = i >> 9, kk = i & 511;
        int gr = (rr >> 2) * 512 + cta * 4 + (rr & 3);
        W_s[rr * 516 + kk] = W_hh[(size_t)gr * 512 + kk];
    }
    if (tid < 128) c_s[tid >> 2][tid & 3] = 0.f;
    __syncthreads();

    const float4* Wr4 = (const float4*)(W_s + r * 516);
    const float4* H04 = (const float4*)(h_s + b0 * 512);
    const float4* H14 = (const float4*)(h_s + b1 * 512);

    for (int t = 0; t < LL; t++) {
        if (t > 0) {
            // broadcast h[t-1] for all 32 batches into SMEM (L2-only loads)
            for (int i = tid; i < 32 * 128; i += 256) {
                int b = i >> 7, kq = i & 127;
                ((float4*)h_s)[b * 128 + kq] =
                    __ldcg(((const float4*)hout) + ((size_t)b * LL + (t - 1)) * 128 + kq);
            }
        }
        __syncthreads();

        float4 A0 = make_float4(0,0,0,0), A1 = make_float4(0,0,0,0);
        if (t > 0) {
            #pragma unroll 8
            for (int kq = 0; kq < 128; kq++) {
                float4 w  = Wr4[kq];
                float4 x0 = H04[kq];
                float4 x1 = H14[kq];
                A0.x += w.x * x0.x; A0.y += w.y * x0.y;
                A0.z += w.z * x0.z; A0.w += w.w * x0.w;
                A1.x += w.x * x1.x; A1.y += w.y * x1.y;
                A1.z += w.z * x1.z; A1.w += w.w * x1.w;
            }
        }
        float acc0 = (A0.x + A0.y) + (A0.z + A0.w);
        float acc1 = (A1.x + A1.y) + (A1.z + A1.w);
        acc0 += __ldg(xpre + ((size_t)b0 * LL + t) * G4 + grow);
        acc1 += __ldg(xpre + ((size_t)b1 * LL + t) * G4 + grow);
        gate_s[b0][r] = acc0;
        gate_s[b1][r] = acc1;
        __syncthreads();

        if (tid < 128) {
            int b = tid >> 2, u = tid & 3;
            float gi = gate_s[b][u];
            float gf = gate_s[b][4 + u];
            float gc = gate_s[b][8 + u];
            float go = gate_s[b][12 + u];
            float i_ = 1.f / (1.f + expf(-gi));
            float f_ = 1.f / (1.f + expf(-gf));
            float gg = tanhf(gc);
            float o_ = 1.f / (1.f + expf(-go));
            float c  = f_ * c_s[b][u] + i_ * gg;
            c_s[b][u] = c;
            hout[((size_t)b * LL + t) * HID + cta * 4 + u] = o_ * tanhf(c);
        }
        grid_barrier(LCTAS);
    }
}

// ---------------- att[m] = attT[m,:] . sim_W --------------------------------
__global__ void att_reduce(const float* __restrict__ attT,
                           const float* __restrict__ simW,
                           float* __restrict__ att)
{
    int gid  = blockIdx.x * blockDim.x + threadIdx.x;
    int row  = gid >> 5;
    int lane = threadIdx.x & 31;
    if (row >= BLROWS) return;
    float v = 0.f;
    for (int a = lane; a < ATTD; a += 32)
        v += attT[(size_t)row * ATTD + a] * simW[a];
    #pragma unroll
    for (int o = 16; o; o >>= 1) v += __shfl_down_sync(0xffffffffu, v, o);
    if (lane == 0) att[row] = v;
}

// ---------------- causal attention via online-softmax prefix scan -----------
// alphas[b,i,j] = exp(att[b,j]) / sum_{k<=i} exp(att[b,k])  (j<=i)
// attn_out[b,i] = prefix_num / prefix_den; attn_cum_1 = exclusive cumsum.
// Writes final[b,i] = [attn_cum_1 (512), out (512)].
__global__ void attn_scan(const float* __restrict__ att,
                          const float* __restrict__ out,
                          float* __restrict__ finalbuf)
{
    int b = blockIdx.x;          // 32 blocks
    int h = threadIdx.x;         // 512 threads
    __shared__ float s_att[LL];
    for (int i = h; i < LL; i += 512) s_att[i] = att[(size_t)b * LL + i];
    __syncthreads();

    const float* ob = out      + (size_t)b * LL * HID;
    float*       fb = finalbuf + (size_t)b * LL * (2 * HID);

    float m = -1e30f, den = 0.f, num = 0.f, cum = 0.f;
    for (int i = 0; i < LL; i++) {
        float s     = s_att[i];
        float mnew  = fmaxf(m, s);
        float scale = expf(m - mnew);
        float alpha = expf(s - mnew);
        float ov    = ob[(size_t)i * HID + h];
        num = num * scale + alpha * ov;
        den = den * scale + alpha;
        m   = mnew;
        fb[(size_t)i * (2 * HID) + h]       = cum;   // attn_cum_1 (exclusive)
        fb[(size_t)i * (2 * HID) + HID + h] = ov;    // out
        cum += num / den;
    }
}

// ---------------- launch -----------------------------------------------------
extern "C" void kernel_launch(void* const* d_in, const int* in_sizes, int n_in,
                              void* d_out, int out_size)
{
    const int*   skill        = (const int*)  d_in[0];
    const int*   answer       = (const int*)  d_in[1];
    const float* skill_table  = (const float*)d_in[2];
    const float* answer_table = (const float*)d_in[3];
    const float* W_ih         = (const float*)d_in[4];
    const float* W_hh         = (const float*)d_in[5];
    const float* b_ih         = (const float*)d_in[6];
    const float* b_hh         = (const float*)d_in[7];
    const float* mlp_W        = (const float*)d_in[8];
    const float* mlp_b        = (const float*)d_in[9];
    const float* sim_W        = (const float*)d_in[10];
    const float* fc_W         = (const float*)d_in[11];
    const float* fc_b         = (const float*)d_in[12];
    float* outp = (float*)d_out;

    float *p_sae, *p_xpre, *p_hout, *p_attT, *p_att, *p_final;
    cudaGetSymbolAddress((void**)&p_sae,   g_sae);
    cudaGetSymbolAddress((void**)&p_xpre,  g_xpre);
    cudaGetSymbolAddress((void**)&p_hout,  g_hout);
    cudaGetSymbolAddress((void**)&p_attT,  g_attT);
    cudaGetSymbolAddress((void**)&p_att,   g_att);
    cudaGetSymbolAddress((void**)&p_final, g_final);

    // 1) embeddings -> sae
    {
        int total = BLROWS * 128;
        embed_kernel<<<total / 256, 256>>>(skill, answer, skill_table, answer_table);
    }

    // 2) x_pre = sae @ W_ih^T + (b_ih + b_hh)
    {
        dim3 grid(G4 / 128, BLROWS / 128);
        sgemm_nt<0><<<grid, 256>>>(p_sae, W_ih, b_ih, b_hh, p_xpre,
                                   BLROWS, G4, HID);
    }

    // 3) LSTM recurrence (persistent, grid barrier)
    {
        const int smem = (16 * 516 + 32 * 512) * (int)sizeof(float);  // 98560
        cudaFuncSetAttribute(lstm_kernel,
                             cudaFuncAttributeMaxDynamicSharedMemorySize, smem);
        lstm_kernel<<<LCTAS, 256, smem>>>(p_xpre, W_hh, p_hout);
    }

    // 4) attT = tanh(out @ mlp_W^T + mlp_b)
    {
        dim3 grid((ATTD + 127) / 128, BLROWS / 128);
        sgemm_nt<1><<<grid, 256>>>(p_hout, mlp_W, mlp_b, nullptr, p_attT,
                                   BLROWS, ATTD, HID);
    }

    // 5) att = attT . sim_W
    att_reduce<<<(BLROWS * 32) / 256, 256>>>(p_attT, sim_W, p_att);

    // 6) online-softmax prefix scan -> final = [attn_cum_1, out]
    attn_scan<<<BB, 512>>>(p_att, p_hout, p_final);

    // 7) res = sigmoid(final @ fc_W^T + fc_b)
    {
        dim3 grid((NUMC + 127) / 128, BLROWS / 128);
        sgemm_nt<2><<<grid, 256>>>(p_final, fc_W, fc_b, nullptr, outp,
                                   BLROWS, NUMC, 2 * HID);
    }
}